// round 9
// baseline (speedup 1.0000x reference)
#include <cuda_runtime.h>
#include <cuda_bf16.h>
#include <cstdint>

#define MAXN 100000
#define MAXE 1600000
#define DIN  128

// ---------------------------------------------------------------------------
// Scratch (allocation-free rule: __device__ globals)
// ---------------------------------------------------------------------------
__device__ float g_dinv[MAXN];
__device__ int   g_deg[MAXN];
__device__ int   g_rowptr[MAXN];
__device__ int   g_cursor[MAXN];
__device__ int   g_csrc[MAXE];
__device__ int   g_src[MAXE];
__device__ int   g_dst[MAXE];
__device__ int   g_bsum[128];
__device__ int   g_boff[128];
__device__ int   g_is32;
__device__ float g_bufA[(size_t)MAXN * 128];
__device__ float g_bufB[(size_t)MAXN * 128];
// Pre-split weights: W1(128x128), W2(128x128), W3(64x128) -> 320*128 elems
__device__ __nv_bfloat16 g_wh[320 * 128];
__device__ __nv_bfloat16 g_wl[320 * 128];

// ---------------------------------------------------------------------------
// Init: zero degree histogram + reset dtype flag
// ---------------------------------------------------------------------------
__global__ void k_init(int n) {
    int i = blockIdx.x * blockDim.x + threadIdx.x;
    if (i < n) g_deg[i] = 0;
    if (i == 0) g_is32 = 0;
}

// Probe 512 int64-words: for int32 data these fuse (src[2i],src[2i+1]) pairs
// and are out of [0,n) with overwhelming probability.
__global__ void k_probe(const long long* __restrict__ raw, int cnt, int n) {
    int i = blockIdx.x * blockDim.x + threadIdx.x;
    if (i < cnt) {
        long long v = raw[i];
        if (v < 0 || v >= (long long)n) g_is32 = 1;
    }
}

__global__ void k_convert_hist(const void* __restrict__ raw, int e) {
    int i = blockIdx.x * blockDim.x + threadIdx.x;
    if (i >= e) return;
    int s, d;
    if (g_is32) {
        const int* p = (const int*)raw;
        s = p[i]; d = p[e + i];
    } else {
        const long long* p = (const long long*)raw;
        s = (int)p[i]; d = (int)p[e + i];
    }
    g_src[i] = s; g_dst[i] = d;
    atomicAdd(&g_deg[d], 1);
}

// ---------------------------------------------------------------------------
// CSR build: exclusive scan + fill
// ---------------------------------------------------------------------------
__global__ void k_scan1(int n) {
    __shared__ int sm[1024];
    int i = blockIdx.x * 1024 + threadIdx.x;
    int v = (i < n) ? g_deg[i] : 0;
    sm[threadIdx.x] = v;
    __syncthreads();
#pragma unroll
    for (int off = 1; off < 1024; off <<= 1) {
        int t = (threadIdx.x >= off) ? sm[threadIdx.x - off] : 0;
        __syncthreads();
        sm[threadIdx.x] += t;
        __syncthreads();
    }
    if (i < n) g_rowptr[i] = sm[threadIdx.x] - v;
    if (threadIdx.x == 1023) g_bsum[blockIdx.x] = sm[1023];
}

__global__ void k_scan2(int nb) {
    __shared__ int sm[128];
    int v = (threadIdx.x < nb) ? g_bsum[threadIdx.x] : 0;
    sm[threadIdx.x] = v;
    __syncthreads();
#pragma unroll
    for (int off = 1; off < 128; off <<= 1) {
        int t = (threadIdx.x >= off) ? sm[threadIdx.x - off] : 0;
        __syncthreads();
        sm[threadIdx.x] += t;
        __syncthreads();
    }
    if (threadIdx.x < nb) g_boff[threadIdx.x] = sm[threadIdx.x] - v;
}

__global__ void k_scan3(int n) {   // + fused rsqrt normalization
    int i = blockIdx.x * blockDim.x + threadIdx.x;
    if (i < n) {
        int r = g_rowptr[i] + g_boff[i >> 10];
        g_rowptr[i] = r;
        g_cursor[i] = r;
        g_dinv[i] = rsqrtf((float)g_deg[i] + 1.0f);
    }
}

__global__ void k_fill(int e) {
    int i = blockIdx.x * blockDim.x + threadIdx.x;
    if (i >= e) return;
    int d = g_dst[i];
    int pos = atomicAdd(&g_cursor[d], 1);
    g_csrc[pos] = g_src[i];
}

// ---------------------------------------------------------------------------
// Weight split: W (fp32) -> hi/lo bf16
// ---------------------------------------------------------------------------
__global__ void k_prep_w(const float* __restrict__ W1, const float* __restrict__ W2,
                         const float* __restrict__ W3) {
    int i = blockIdx.x * blockDim.x + threadIdx.x;
    if (i >= 320 * 128) return;
    float v;
    if (i < 16384)       v = W1[i];
    else if (i < 32768)  v = W2[i - 16384];
    else                 v = W3[i - 32768];
    __nv_bfloat16 h = __float2bfloat16_rn(v);
    g_wh[i] = h;
    g_wl[i] = __float2bfloat16_rn(v - __bfloat162float(h));
}

// ---------------------------------------------------------------------------
// mma helpers
// ---------------------------------------------------------------------------
__device__ __forceinline__ void mma16816(float* c, const uint32_t* a,
                                         uint32_t b0, uint32_t b1) {
    asm volatile(
        "mma.sync.aligned.m16n8k16.row.col.f32.bf16.bf16.f32 "
        "{%0,%1,%2,%3}, {%4,%5,%6,%7}, {%8,%9}, {%0,%1,%2,%3};"
        : "+f"(c[0]), "+f"(c[1]), "+f"(c[2]), "+f"(c[3])
        : "r"(a[0]), "r"(a[1]), "r"(a[2]), "r"(a[3]), "r"(b0), "r"(b1));
}

__device__ __forceinline__ void split_store(__nv_bfloat16* hi, __nv_bfloat16* lo,
                                            float4 v) {
    __nv_bfloat162 h01 = __floats2bfloat162_rn(v.x, v.y);
    __nv_bfloat162 h23 = __floats2bfloat162_rn(v.z, v.w);
    float2 f01 = __bfloat1622float2(h01);
    float2 f23 = __bfloat1622float2(h23);
    __nv_bfloat162 l01 = __floats2bfloat162_rn(v.x - f01.x, v.y - f01.y);
    __nv_bfloat162 l23 = __floats2bfloat162_rn(v.z - f23.x, v.w - f23.y);
    *(uint2*)hi = make_uint2(*(uint32_t*)&h01, *(uint32_t*)&h23);
    *(uint2*)lo = make_uint2(*(uint32_t*)&l01, *(uint32_t*)&l23);
}

// Warp-level gather-aggregate for one node (fp32, width 128, lane owns 4 cols).
__device__ __forceinline__ float4 warp_agg(const float* __restrict__ H,
                                           int node, int lane) {
    int beg = g_rowptr[node];
    int end = beg + g_deg[node];
    float4 acc = make_float4(0.f, 0.f, 0.f, 0.f);
    int j = beg;
    for (; j + 4 <= end; j += 4) {
        int s0 = g_csrc[j], s1 = g_csrc[j + 1];
        int s2 = g_csrc[j + 2], s3 = g_csrc[j + 3];
        float w0 = g_dinv[s0], w1 = g_dinv[s1];
        float w2 = g_dinv[s2], w3 = g_dinv[s3];
        float4 v0 = *(const float4*)&H[(size_t)s0 * 128 + lane * 4];
        float4 v1 = *(const float4*)&H[(size_t)s1 * 128 + lane * 4];
        float4 v2 = *(const float4*)&H[(size_t)s2 * 128 + lane * 4];
        float4 v3 = *(const float4*)&H[(size_t)s3 * 128 + lane * 4];
        acc.x += w0 * v0.x + w1 * v1.x + w2 * v2.x + w3 * v3.x;
        acc.y += w0 * v0.y + w1 * v1.y + w2 * v2.y + w3 * v3.y;
        acc.z += w0 * v0.z + w1 * v1.z + w2 * v2.z + w3 * v3.z;
        acc.w += w0 * v0.w + w1 * v1.w + w2 * v2.w + w3 * v3.w;
    }
    for (; j < end; j++) {
        int s = g_csrc[j];
        float w = g_dinv[s];
        float4 v = *(const float4*)&H[(size_t)s * 128 + lane * 4];
        acc.x += w * v.x; acc.y += w * v.y;
        acc.z += w * v.z; acc.w += w * v.w;
    }
    return acc;
}

// ---------------------------------------------------------------------------
// Layer-1 GEMM: H = X @ W^T (no agg on input)
// ---------------------------------------------------------------------------
template <int FOUT>
__global__ void __launch_bounds__(256, 1) k_mma1(
    const float* __restrict__ X, const __nv_bfloat16* __restrict__ Wh,
    const __nv_bfloat16* __restrict__ Wl, float* __restrict__ H, int n)
{
    constexpr int RS = 136;
    constexpr int NT = FOUT / 8;
    extern __shared__ __nv_bfloat16 sm[];
    __nv_bfloat16* Ah = sm;
    __nv_bfloat16* Al = Ah + 8 * 16 * RS;
    __nv_bfloat16* Bh = Al + 8 * 16 * RS;
    __nv_bfloat16* Bl = Bh + FOUT * RS;

    const int tid = threadIdx.x, wid = tid >> 5, lane = tid & 31;
    const int row0 = blockIdx.x * 128;

    for (int idx = tid; idx < FOUT * 32; idx += 256) {
        int r = idx >> 5, c4 = idx & 31;
        *(uint2*)&Bh[r * RS + c4 * 4] = *(const uint2*)&Wh[r * 128 + c4 * 4];
        *(uint2*)&Bl[r * RS + c4 * 4] = *(const uint2*)&Wl[r * 128 + c4 * 4];
    }

    __nv_bfloat16* Awh = Ah + wid * 16 * RS;
    __nv_bfloat16* Awl = Al + wid * 16 * RS;
    for (int idx = lane; idx < 16 * 32; idx += 32) {
        int r = idx >> 5, c4 = idx & 31;
        int grow = row0 + wid * 16 + r;
        float4 v = make_float4(0.f, 0.f, 0.f, 0.f);
        if (grow < n) v = *(const float4*)&X[(size_t)grow * 128 + c4 * 4];
        split_store(&Awh[r * RS + c4 * 4], &Awl[r * RS + c4 * 4], v);
    }
    __syncthreads();

    float acc[NT][4];
#pragma unroll
    for (int t = 0; t < NT; t++)
#pragma unroll
        for (int j = 0; j < 4; j++) acc[t][j] = 0.f;

    const int qr = lane >> 2, qc = (lane & 3) * 2;

#pragma unroll
    for (int ks = 0; ks < 8; ks++) {
        const int kb = ks * 16;
        uint32_t ah[4], al[4];
        ah[0] = *(const uint32_t*)&Awh[(qr)     * RS + kb + qc];
        ah[1] = *(const uint32_t*)&Awh[(qr + 8) * RS + kb + qc];
        ah[2] = *(const uint32_t*)&Awh[(qr)     * RS + kb + 8 + qc];
        ah[3] = *(const uint32_t*)&Awh[(qr + 8) * RS + kb + 8 + qc];
        al[0] = *(const uint32_t*)&Awl[(qr)     * RS + kb + qc];
        al[1] = *(const uint32_t*)&Awl[(qr + 8) * RS + kb + qc];
        al[2] = *(const uint32_t*)&Awl[(qr)     * RS + kb + 8 + qc];
        al[3] = *(const uint32_t*)&Awl[(qr + 8) * RS + kb + 8 + qc];
#pragma unroll
        for (int nt = 0; nt < NT; nt++) {
            int nr = nt * 8 + qr;
            uint32_t bh0 = *(const uint32_t*)&Bh[nr * RS + kb + qc];
            uint32_t bh1 = *(const uint32_t*)&Bh[nr * RS + kb + 8 + qc];
            mma16816(acc[nt], ah, bh0, bh1);
            mma16816(acc[nt], al, bh0, bh1);
            uint32_t bl0 = *(const uint32_t*)&Bl[nr * RS + kb + qc];
            uint32_t bl1 = *(const uint32_t*)&Bl[nr * RS + kb + 8 + qc];
            mma16816(acc[nt], ah, bl0, bl1);
        }
    }

    const int r0 = row0 + wid * 16 + qr;
    const int r1 = r0 + 8;
#pragma unroll
    for (int nt = 0; nt < NT; nt++) {
        int col = nt * 8 + qc;
        if (r0 < n)
            *(float2*)&H[(size_t)r0 * FOUT + col] = make_float2(acc[nt][0], acc[nt][1]);
        if (r1 < n)
            *(float2*)&H[(size_t)r1 * FOUT + col] = make_float2(acc[nt][2], acc[nt][3]);
    }
}

// ---------------------------------------------------------------------------
// Fused agg + GEMM: A-row = relu(bias + dinv*(agg + dinv*Hprev[row])); H = A @ W^T
// Hprev has width 128.
// ---------------------------------------------------------------------------
template <int FOUT>
__global__ void __launch_bounds__(256, 1) k_aggmma(
    const float* __restrict__ Hprev, const float* __restrict__ bias,
    const __nv_bfloat16* __restrict__ Wh, const __nv_bfloat16* __restrict__ Wl,
    float* __restrict__ H, int n)
{
    constexpr int RS = 136;
    constexpr int NT = FOUT / 8;
    extern __shared__ __nv_bfloat16 sm[];
    __nv_bfloat16* Ah = sm;
    __nv_bfloat16* Al = Ah + 8 * 16 * RS;
    __nv_bfloat16* Bh = Al + 8 * 16 * RS;
    __nv_bfloat16* Bl = Bh + FOUT * RS;

    const int tid = threadIdx.x, wid = tid >> 5, lane = tid & 31;
    const int row0 = blockIdx.x * 128;

    for (int idx = tid; idx < FOUT * 32; idx += 256) {
        int r = idx >> 5, c4 = idx & 31;
        *(uint2*)&Bh[r * RS + c4 * 4] = *(const uint2*)&Wh[r * 128 + c4 * 4];
        *(uint2*)&Bl[r * RS + c4 * 4] = *(const uint2*)&Wl[r * 128 + c4 * 4];
    }

    // ---- A-phase: aggregate 16 rows per warp, relu, split to bf16 ----
    __nv_bfloat16* Awh = Ah + wid * 16 * RS;
    __nv_bfloat16* Awl = Al + wid * 16 * RS;
    float4 bb = *(const float4*)&bias[lane * 4];
    for (int r = 0; r < 16; r++) {
        int node = row0 + wid * 16 + r;
        float4 o = make_float4(0.f, 0.f, 0.f, 0.f);
        if (node < n) {
            float4 acc = warp_agg(Hprev, node, lane);
            float di = g_dinv[node];
            float4 hs = *(const float4*)&Hprev[(size_t)node * 128 + lane * 4];
            o.x = fmaxf(bb.x + di * (acc.x + di * hs.x), 0.f);
            o.y = fmaxf(bb.y + di * (acc.y + di * hs.y), 0.f);
            o.z = fmaxf(bb.z + di * (acc.z + di * hs.z), 0.f);
            o.w = fmaxf(bb.w + di * (acc.w + di * hs.w), 0.f);
        }
        split_store(&Awh[r * RS + lane * 4], &Awl[r * RS + lane * 4], o);
    }
    __syncthreads();

    float acc[NT][4];
#pragma unroll
    for (int t = 0; t < NT; t++)
#pragma unroll
        for (int j = 0; j < 4; j++) acc[t][j] = 0.f;

    const int qr = lane >> 2, qc = (lane & 3) * 2;

#pragma unroll
    for (int ks = 0; ks < 8; ks++) {
        const int kb = ks * 16;
        uint32_t ah[4], al[4];
        ah[0] = *(const uint32_t*)&Awh[(qr)     * RS + kb + qc];
        ah[1] = *(const uint32_t*)&Awh[(qr + 8) * RS + kb + qc];
        ah[2] = *(const uint32_t*)&Awh[(qr)     * RS + kb + 8 + qc];
        ah[3] = *(const uint32_t*)&Awh[(qr + 8) * RS + kb + 8 + qc];
        al[0] = *(const uint32_t*)&Awl[(qr)     * RS + kb + qc];
        al[1] = *(const uint32_t*)&Awl[(qr + 8) * RS + kb + qc];
        al[2] = *(const uint32_t*)&Awl[(qr)     * RS + kb + 8 + qc];
        al[3] = *(const uint32_t*)&Awl[(qr + 8) * RS + kb + 8 + qc];
#pragma unroll
        for (int nt = 0; nt < NT; nt++) {
            int nr = nt * 8 + qr;
            uint32_t bh0 = *(const uint32_t*)&Bh[nr * RS + kb + qc];
            uint32_t bh1 = *(const uint32_t*)&Bh[nr * RS + kb + 8 + qc];
            mma16816(acc[nt], ah, bh0, bh1);
            mma16816(acc[nt], al, bh0, bh1);
            uint32_t bl0 = *(const uint32_t*)&Bl[nr * RS + kb + qc];
            uint32_t bl1 = *(const uint32_t*)&Bl[nr * RS + kb + 8 + qc];
            mma16816(acc[nt], ah, bl0, bl1);
        }
    }

    const int r0 = row0 + wid * 16 + qr;
    const int r1 = r0 + 8;
#pragma unroll
    for (int nt = 0; nt < NT; nt++) {
        int col = nt * 8 + qc;
        if (r0 < n)
            *(float2*)&H[(size_t)r0 * FOUT + col] = make_float2(acc[nt][0], acc[nt][1]);
        if (r1 < n)
            *(float2*)&H[(size_t)r1 * FOUT + col] = make_float2(acc[nt][2], acc[nt][3]);
    }
}

// ---------------------------------------------------------------------------
// Final aggregation (width 64): writes mu and logstd (duplicate).
// ---------------------------------------------------------------------------
__global__ void __launch_bounds__(256) k_agg64(
    const float* __restrict__ H, const float* __restrict__ bias,
    float* __restrict__ OUT, int n)
{
    int node = blockIdx.x * 8 + (threadIdx.x >> 5);
    if (node >= n) return;
    int lane = threadIdx.x & 31;

    int beg = g_rowptr[node];
    int end = beg + g_deg[node];

    float2 acc = make_float2(0.f, 0.f);
    int j = beg;
    for (; j + 4 <= end; j += 4) {
        int s0 = g_csrc[j], s1 = g_csrc[j + 1];
        int s2 = g_csrc[j + 2], s3 = g_csrc[j + 3];
        float w0 = g_dinv[s0], w1 = g_dinv[s1];
        float w2 = g_dinv[s2], w3 = g_dinv[s3];
        float2 v0 = *(const float2*)&H[(size_t)s0 * 64 + lane * 2];
        float2 v1 = *(const float2*)&H[(size_t)s1 * 64 + lane * 2];
        float2 v2 = *(const float2*)&H[(size_t)s2 * 64 + lane * 2];
        float2 v3 = *(const float2*)&H[(size_t)s3 * 64 + lane * 2];
        acc.x += w0 * v0.x + w1 * v1.x + w2 * v2.x + w3 * v3.x;
        acc.y += w0 * v0.y + w1 * v1.y + w2 * v2.y + w3 * v3.y;
    }
    for (; j < end; j++) {
        int s = g_csrc[j];
        float w = g_dinv[s];
        float2 v = *(const float2*)&H[(size_t)s * 64 + lane * 2];
        acc.x += w * v.x; acc.y += w * v.y;
    }

    float di = g_dinv[node];
    float2 hs = *(const float2*)&H[(size_t)node * 64 + lane * 2];
    float2 bb = *(const float2*)&bias[lane * 2];
    float2 o;
    o.x = bb.x + di * (acc.x + di * hs.x);
    o.y = bb.y + di * (acc.y + di * hs.y);
    *(float2*)&OUT[(size_t)node * 64 + lane * 2] = o;         // mu
    *(float2*)&OUT[(size_t)(n + node) * 64 + lane * 2] = o;   // logstd
}

// ---------------------------------------------------------------------------
extern "C" void kernel_launch(void* const* d_in, const int* in_sizes, int n_in,
                              void* d_out, int out_size)
{
    const float* x  = (const float*)d_in[0];
    const float* W1 = (const float*)d_in[1];
    const float* b1 = (const float*)d_in[2];
    const float* W2 = (const float*)d_in[3];
    const float* b2 = (const float*)d_in[4];
    const float* W3 = (const float*)d_in[5];
    const float* b3 = (const float*)d_in[6];
    const void*  ei = d_in[7];

    int n = in_sizes[0] / DIN;
    int e = in_sizes[7] / 2;
    float* out = (float*)d_out;

    float *bufA, *bufB;
    cudaGetSymbolAddress((void**)&bufA, g_bufA);
    cudaGetSymbolAddress((void**)&bufB, g_bufB);
    __nv_bfloat16 *wh, *wl;
    cudaGetSymbolAddress((void**)&wh, g_wh);
    cudaGetSymbolAddress((void**)&wl, g_wl);

    constexpr int RS = 136;
    const int SMEM128 = (8 * 16 * RS * 2 + 128 * RS * 2) * 2;  // ~136 KB
    const int SMEM64  = (8 * 16 * RS * 2 + 64 * RS * 2) * 2;   // ~102 KB
    cudaFuncSetAttribute(k_mma1<128>,
                         cudaFuncAttributeMaxDynamicSharedMemorySize, SMEM128);
    cudaFuncSetAttribute(k_aggmma<128>,
                         cudaFuncAttributeMaxDynamicSharedMemorySize, SMEM128);
    cudaFuncSetAttribute(k_aggmma<64>,
                         cudaFuncAttributeMaxDynamicSharedMemorySize, SMEM64);

    int nb  = (n + 255) / 256;
    int ebk = (e + 255) / 256;
    int nsb = (n + 1023) / 1024;

    // --- preprocessing ---
    k_init<<<nb, 256>>>(n);
    k_probe<<<2, 256>>>((const long long*)ei, 512 < e ? 512 : e, n);
    k_convert_hist<<<ebk, 256>>>(ei, e);
    k_scan1<<<nsb, 1024>>>(n);
    k_scan2<<<1, 128>>>(nsb);
    k_scan3<<<nb, 256>>>(n);
    k_fill<<<ebk, 256>>>(e);
    k_prep_w<<<160, 256>>>(W1, W2, W3);

    int gb = (n + 127) / 128;
    int ag = (n + 7) / 8;

    // Layer 1: H1 = x @ W1^T
    k_mma1<128><<<gb, 256, SMEM128>>>(x, wh, wl, bufA, n);
    // Layer 2 fused: A = relu(agg(H1)+b1); H2 = A @ W2^T
    k_aggmma<128><<<gb, 256, SMEM128>>>(bufA, b1, wh + 16384, wl + 16384, bufB, n);
    // Layer 3 fused: A = relu(agg(H2)+b2); H3 = A @ W3^T
    k_aggmma<64><<<gb, 256, SMEM64>>>(bufB, b2, wh + 32768, wl + 32768, bufA, n);
    // Final aggregation -> mu & logstd
    k_agg64<<<ag, 256>>>(bufA, b3, out, n);
}

// round 10
// speedup vs baseline: 1.3904x; 1.3904x over previous
#include <cuda_runtime.h>
#include <cuda_bf16.h>
#include <cstdint>

#define MAXN 100000
#define MAXE 1600000
#define DIN  128

// ---------------------------------------------------------------------------
// Scratch (allocation-free rule: __device__ globals)
// ---------------------------------------------------------------------------
__device__ float g_dinv[MAXN];
__device__ int   g_deg[MAXN];
__device__ int   g_rowptr[MAXN];
__device__ int   g_cursor[MAXN];
__device__ int   g_csrc[MAXE];
__device__ int   g_bsum[128];
__device__ int   g_boff[128];
__device__ int   g_is32 = 0;   // static init; only ever transitions 0->1 for
                               // the same input data => deterministic replays
__device__ float g_bufA[(size_t)MAXN * 128];
__device__ float g_bufB[(size_t)MAXN * 128];
// Pre-split weights: W1(128x128), W2(128x128), W3(64x128) -> 320*128 elems
__device__ __nv_bfloat16 g_wh[320 * 128];
__device__ __nv_bfloat16 g_wl[320 * 128];

// ---------------------------------------------------------------------------
// Zero degree histogram + dtype probe (first 512 int64-words; for int32 data
// they fuse (src[2i],src[2i+1]) pairs and fall out of [0,n) w.h.p.)
// ---------------------------------------------------------------------------
__global__ void k_zero_probe(const long long* __restrict__ raw, int pcnt, int n) {
    int i = blockIdx.x * blockDim.x + threadIdx.x;
    if (i < n) g_deg[i] = 0;
    if (i < pcnt) {
        long long v = raw[i];
        if (v < 0 || v >= (long long)n) g_is32 = 1;
    }
}

__global__ void k_hist(const void* __restrict__ raw, int e) {
    int i = blockIdx.x * blockDim.x + threadIdx.x;
    if (i >= e) return;
    int d = g_is32 ? ((const int*)raw)[e + i]
                   : (int)((const long long*)raw)[e + i];
    atomicAdd(&g_deg[d], 1);
}

// ---------------------------------------------------------------------------
// CSR build: exclusive scan + fill
// ---------------------------------------------------------------------------
__global__ void k_scan1(int n) {
    __shared__ int sm[1024];
    int i = blockIdx.x * 1024 + threadIdx.x;
    int v = (i < n) ? g_deg[i] : 0;
    sm[threadIdx.x] = v;
    __syncthreads();
#pragma unroll
    for (int off = 1; off < 1024; off <<= 1) {
        int t = (threadIdx.x >= off) ? sm[threadIdx.x - off] : 0;
        __syncthreads();
        sm[threadIdx.x] += t;
        __syncthreads();
    }
    if (i < n) g_rowptr[i] = sm[threadIdx.x] - v;
    if (threadIdx.x == 1023) g_bsum[blockIdx.x] = sm[1023];
}

__global__ void k_scan2(int nb) {
    __shared__ int sm[128];
    int v = (threadIdx.x < nb) ? g_bsum[threadIdx.x] : 0;
    sm[threadIdx.x] = v;
    __syncthreads();
#pragma unroll
    for (int off = 1; off < 128; off <<= 1) {
        int t = (threadIdx.x >= off) ? sm[threadIdx.x - off] : 0;
        __syncthreads();
        sm[threadIdx.x] += t;
        __syncthreads();
    }
    if (threadIdx.x < nb) g_boff[threadIdx.x] = sm[threadIdx.x] - v;
}

__global__ void k_scan3(int n) {   // + fused rsqrt normalization
    int i = blockIdx.x * blockDim.x + threadIdx.x;
    if (i < n) {
        int r = g_rowptr[i] + g_boff[i >> 10];
        g_rowptr[i] = r;
        g_cursor[i] = r;
        g_dinv[i] = rsqrtf((float)g_deg[i] + 1.0f);
    }
}

__global__ void k_fill(const void* __restrict__ raw, int e) {
    int i = blockIdx.x * blockDim.x + threadIdx.x;
    if (i >= e) return;
    int s, d;
    if (g_is32) {
        const int* p = (const int*)raw;
        s = p[i]; d = p[e + i];
    } else {
        const long long* p = (const long long*)raw;
        s = (int)p[i]; d = (int)p[e + i];
    }
    int pos = atomicAdd(&g_cursor[d], 1);
    g_csrc[pos] = s;
}

// ---------------------------------------------------------------------------
// Weight split: W (fp32) -> hi/lo bf16
// ---------------------------------------------------------------------------
__global__ void k_prep_w(const float* __restrict__ W1, const float* __restrict__ W2,
                         const float* __restrict__ W3) {
    int i = blockIdx.x * blockDim.x + threadIdx.x;
    if (i >= 320 * 128) return;
    float v;
    if (i < 16384)       v = W1[i];
    else if (i < 32768)  v = W2[i - 16384];
    else                 v = W3[i - 32768];
    __nv_bfloat16 h = __float2bfloat16_rn(v);
    g_wh[i] = h;
    g_wl[i] = __float2bfloat16_rn(v - __bfloat162float(h));
}

// ---------------------------------------------------------------------------
// mma.sync bf16 split GEMM: H[128 x FOUT tile] = act(X) @ W^T
// D = Ahi*Bhi + Alo*Bhi + Ahi*Blo  (fp32 accumulate, lo*lo dropped ~2^-16)
// ---------------------------------------------------------------------------
__device__ __forceinline__ void mma16816(float* c, const uint32_t* a,
                                         uint32_t b0, uint32_t b1) {
    asm volatile(
        "mma.sync.aligned.m16n8k16.row.col.f32.bf16.bf16.f32 "
        "{%0,%1,%2,%3}, {%4,%5,%6,%7}, {%8,%9}, {%0,%1,%2,%3};"
        : "+f"(c[0]), "+f"(c[1]), "+f"(c[2]), "+f"(c[3])
        : "r"(a[0]), "r"(a[1]), "r"(a[2]), "r"(a[3]), "r"(b0), "r"(b1));
}

template <int FOUT, bool RELU>
__global__ void __launch_bounds__(256, 1) k_mma(
    const float* __restrict__ X, const __nv_bfloat16* __restrict__ Wh,
    const __nv_bfloat16* __restrict__ Wl, float* __restrict__ H, int n)
{
    constexpr int RS = 136;     // smem row stride in bf16 (272B: conflict-free)
    constexpr int NT = FOUT / 8;
    extern __shared__ __nv_bfloat16 sm[];
    __nv_bfloat16* Ah = sm;                       // [8][16][RS]
    __nv_bfloat16* Al = Ah + 8 * 16 * RS;
    __nv_bfloat16* Bh = Al + 8 * 16 * RS;         // [FOUT][RS]
    __nv_bfloat16* Bl = Bh + FOUT * RS;

    const int tid = threadIdx.x, wid = tid >> 5, lane = tid & 31;
    const int row0 = blockIdx.x * 128;

    // ---- stage pre-split weights into SMEM ----
    for (int idx = tid; idx < FOUT * 32; idx += 256) {
        int r = idx >> 5, c4 = idx & 31;
        *(uint2*)&Bh[r * RS + c4 * 4] = *(const uint2*)&Wh[r * 128 + c4 * 4];
        *(uint2*)&Bl[r * RS + c4 * 4] = *(const uint2*)&Wl[r * 128 + c4 * 4];
    }

    // ---- each warp converts its 16 fp32 rows -> hi/lo bf16 (ReLU fused) ----
    __nv_bfloat16* Awh = Ah + wid * 16 * RS;
    __nv_bfloat16* Awl = Al + wid * 16 * RS;
    for (int idx = lane; idx < 16 * 32; idx += 32) {
        int r = idx >> 5, c4 = idx & 31;
        int grow = row0 + wid * 16 + r;
        float4 v = make_float4(0.f, 0.f, 0.f, 0.f);
        if (grow < n) {
            v = *(const float4*)&X[(size_t)grow * 128 + c4 * 4];
            if (RELU) {
                v.x = fmaxf(v.x, 0.f); v.y = fmaxf(v.y, 0.f);
                v.z = fmaxf(v.z, 0.f); v.w = fmaxf(v.w, 0.f);
            }
        }
        __nv_bfloat162 h01 = __floats2bfloat162_rn(v.x, v.y);
        __nv_bfloat162 h23 = __floats2bfloat162_rn(v.z, v.w);
        float2 f01 = __bfloat1622float2(h01);
        float2 f23 = __bfloat1622float2(h23);
        __nv_bfloat162 l01 = __floats2bfloat162_rn(v.x - f01.x, v.y - f01.y);
        __nv_bfloat162 l23 = __floats2bfloat162_rn(v.z - f23.x, v.w - f23.y);
        *(uint2*)&Awh[r * RS + c4 * 4] =
            make_uint2(*(uint32_t*)&h01, *(uint32_t*)&h23);
        *(uint2*)&Awl[r * RS + c4 * 4] =
            make_uint2(*(uint32_t*)&l01, *(uint32_t*)&l23);
    }
    __syncthreads();

    float acc[NT][4];
#pragma unroll
    for (int t = 0; t < NT; t++)
#pragma unroll
        for (int j = 0; j < 4; j++) acc[t][j] = 0.f;

    const int qr = lane >> 2;           // quad row
    const int qc = (lane & 3) * 2;      // quad col (k or n offset)

#pragma unroll
    for (int ks = 0; ks < 8; ks++) {
        const int kb = ks * 16;
        uint32_t ah[4], al[4];
        ah[0] = *(const uint32_t*)&Awh[(qr)     * RS + kb + qc];
        ah[1] = *(const uint32_t*)&Awh[(qr + 8) * RS + kb + qc];
        ah[2] = *(const uint32_t*)&Awh[(qr)     * RS + kb + 8 + qc];
        ah[3] = *(const uint32_t*)&Awh[(qr + 8) * RS + kb + 8 + qc];
        al[0] = *(const uint32_t*)&Awl[(qr)     * RS + kb + qc];
        al[1] = *(const uint32_t*)&Awl[(qr + 8) * RS + kb + qc];
        al[2] = *(const uint32_t*)&Awl[(qr)     * RS + kb + 8 + qc];
        al[3] = *(const uint32_t*)&Awl[(qr + 8) * RS + kb + 8 + qc];
#pragma unroll
        for (int nt = 0; nt < NT; nt++) {
            int nr = nt * 8 + qr;
            uint32_t bh0 = *(const uint32_t*)&Bh[nr * RS + kb + qc];
            uint32_t bh1 = *(const uint32_t*)&Bh[nr * RS + kb + 8 + qc];
            mma16816(acc[nt], ah, bh0, bh1);
            mma16816(acc[nt], al, bh0, bh1);
            uint32_t bl0 = *(const uint32_t*)&Bl[nr * RS + kb + qc];
            uint32_t bl1 = *(const uint32_t*)&Bl[nr * RS + kb + 8 + qc];
            mma16816(acc[nt], ah, bl0, bl1);
        }
    }

    // ---- epilogue ----
    const int r0 = row0 + wid * 16 + qr;
    const int r1 = r0 + 8;
#pragma unroll
    for (int nt = 0; nt < NT; nt++) {
        int col = nt * 8 + qc;
        if (r0 < n)
            *(float2*)&H[(size_t)r0 * FOUT + col] = make_float2(acc[nt][0], acc[nt][1]);
        if (r1 < n)
            *(float2*)&H[(size_t)r1 * FOUT + col] = make_float2(acc[nt][2], acc[nt][3]);
    }
}

// ---------------------------------------------------------------------------
// CSR aggregation: one warp per dst node, register accumulation, no atomics.
// OUT[d] = bias + dinv[d] * ( dinv[d]*H[d] + sum_{s in in(d)} dinv[s]*H[s] )
// High occupancy (no smem) is load-bearing: gather phase is L2-latency-bound.
// ---------------------------------------------------------------------------
__global__ void __launch_bounds__(256) k_agg128(
    const float* __restrict__ H, const float* __restrict__ bias,
    float* __restrict__ OUT, int n)
{
    int node = blockIdx.x * 8 + (threadIdx.x >> 5);
    if (node >= n) return;
    int lane = threadIdx.x & 31;

    int beg = g_rowptr[node];
    int end = beg + g_deg[node];

    float4 acc = make_float4(0.f, 0.f, 0.f, 0.f);
    int j = beg;
    for (; j + 4 <= end; j += 4) {
        int s0 = g_csrc[j], s1 = g_csrc[j + 1];
        int s2 = g_csrc[j + 2], s3 = g_csrc[j + 3];
        float w0 = g_dinv[s0], w1 = g_dinv[s1];
        float w2 = g_dinv[s2], w3 = g_dinv[s3];
        float4 v0 = *(const float4*)&H[(size_t)s0 * 128 + lane * 4];
        float4 v1 = *(const float4*)&H[(size_t)s1 * 128 + lane * 4];
        float4 v2 = *(const float4*)&H[(size_t)s2 * 128 + lane * 4];
        float4 v3 = *(const float4*)&H[(size_t)s3 * 128 + lane * 4];
        acc.x += w0 * v0.x + w1 * v1.x + w2 * v2.x + w3 * v3.x;
        acc.y += w0 * v0.y + w1 * v1.y + w2 * v2.y + w3 * v3.y;
        acc.z += w0 * v0.z + w1 * v1.z + w2 * v2.z + w3 * v3.z;
        acc.w += w0 * v0.w + w1 * v1.w + w2 * v2.w + w3 * v3.w;
    }
    for (; j < end; j++) {
        int s = g_csrc[j];
        float w = g_dinv[s];
        float4 v = *(const float4*)&H[(size_t)s * 128 + lane * 4];
        acc.x += w * v.x; acc.y += w * v.y;
        acc.z += w * v.z; acc.w += w * v.w;
    }

    float di = g_dinv[node];
    float4 hs = *(const float4*)&H[(size_t)node * 128 + lane * 4];
    float4 bb = *(const float4*)&bias[lane * 4];
    float4 o;
    o.x = bb.x + di * (acc.x + di * hs.x);
    o.y = bb.y + di * (acc.y + di * hs.y);
    o.z = bb.z + di * (acc.z + di * hs.z);
    o.w = bb.w + di * (acc.w + di * hs.w);
    *(float4*)&OUT[(size_t)node * 128 + lane * 4] = o;
}

__global__ void __launch_bounds__(256) k_agg64(
    const float* __restrict__ H, const float* __restrict__ bias,
    float* __restrict__ OUT, int n)
{
    int node = blockIdx.x * 8 + (threadIdx.x >> 5);
    if (node >= n) return;
    int lane = threadIdx.x & 31;

    int beg = g_rowptr[node];
    int end = beg + g_deg[node];

    float2 acc = make_float2(0.f, 0.f);
    int j = beg;
    for (; j + 4 <= end; j += 4) {
        int s0 = g_csrc[j], s1 = g_csrc[j + 1];
        int s2 = g_csrc[j + 2], s3 = g_csrc[j + 3];
        float w0 = g_dinv[s0], w1 = g_dinv[s1];
        float w2 = g_dinv[s2], w3 = g_dinv[s3];
        float2 v0 = *(const float2*)&H[(size_t)s0 * 64 + lane * 2];
        float2 v1 = *(const float2*)&H[(size_t)s1 * 64 + lane * 2];
        float2 v2 = *(const float2*)&H[(size_t)s2 * 64 + lane * 2];
        float2 v3 = *(const float2*)&H[(size_t)s3 * 64 + lane * 2];
        acc.x += w0 * v0.x + w1 * v1.x + w2 * v2.x + w3 * v3.x;
        acc.y += w0 * v0.y + w1 * v1.y + w2 * v2.y + w3 * v3.y;
    }
    for (; j < end; j++) {
        int s = g_csrc[j];
        float w = g_dinv[s];
        float2 v = *(const float2*)&H[(size_t)s * 64 + lane * 2];
        acc.x += w * v.x; acc.y += w * v.y;
    }

    float di = g_dinv[node];
    float2 hs = *(const float2*)&H[(size_t)node * 64 + lane * 2];
    float2 bb = *(const float2*)&bias[lane * 2];
    float2 o;
    o.x = bb.x + di * (acc.x + di * hs.x);
    o.y = bb.y + di * (acc.y + di * hs.y);
    *(float2*)&OUT[(size_t)node * 64 + lane * 2] = o;         // mu
    *(float2*)&OUT[(size_t)(n + node) * 64 + lane * 2] = o;   // logstd
}

// ---------------------------------------------------------------------------
extern "C" void kernel_launch(void* const* d_in, const int* in_sizes, int n_in,
                              void* d_out, int out_size)
{
    const float* x  = (const float*)d_in[0];
    const float* W1 = (const float*)d_in[1];
    const float* b1 = (const float*)d_in[2];
    const float* W2 = (const float*)d_in[3];
    const float* b2 = (const float*)d_in[4];
    const float* W3 = (const float*)d_in[5];
    const float* b3 = (const float*)d_in[6];
    const void*  ei = d_in[7];

    int n = in_sizes[0] / DIN;
    int e = in_sizes[7] / 2;
    float* out = (float*)d_out;

    float *bufA, *bufB;
    cudaGetSymbolAddress((void**)&bufA, g_bufA);
    cudaGetSymbolAddress((void**)&bufB, g_bufB);
    __nv_bfloat16 *wh, *wl;
    cudaGetSymbolAddress((void**)&wh, g_wh);
    cudaGetSymbolAddress((void**)&wl, g_wl);

    constexpr int RS = 136;
    const int SMEM128 = (8 * 16 * RS * 2 + 128 * RS * 2) * 2;  // ~136 KB
    const int SMEM64  = (8 * 16 * RS * 2 + 64 * RS * 2) * 2;   // ~102 KB
    cudaFuncSetAttribute(k_mma<128, false>,
                         cudaFuncAttributeMaxDynamicSharedMemorySize, SMEM128);
    cudaFuncSetAttribute(k_mma<128, true>,
                         cudaFuncAttributeMaxDynamicSharedMemorySize, SMEM128);
    cudaFuncSetAttribute(k_mma<64, true>,
                         cudaFuncAttributeMaxDynamicSharedMemorySize, SMEM64);

    int nb  = (n + 255) / 256;
    int ebk = (e + 255) / 256;
    int nsb = (n + 1023) / 1024;

    // --- preprocessing: probe dtype, histogram, CSR build, weight split ---
    k_zero_probe<<<nb, 256>>>((const long long*)ei, 512 < e ? 512 : e, n);
    k_hist<<<ebk, 256>>>(ei, e);
    k_scan1<<<nsb, 1024>>>(n);
    k_scan2<<<1, 128>>>(nsb);
    k_scan3<<<nb, 256>>>(n);
    k_fill<<<ebk, 256>>>(ei, e);
    k_prep_w<<<160, 256>>>(W1, W2, W3);

    int gb = (n + 127) / 128;   // GEMM tiles
    int ag = (n + 7) / 8;       // agg blocks

    // Layer 1
    k_mma<128, false><<<gb, 256, SMEM128>>>(x, wh, wl, bufA, n);
    k_agg128<<<ag, 256>>>(bufA, b1, bufB, n);
    // Layer 2
    k_mma<128, true><<<gb, 256, SMEM128>>>(bufB, wh + 16384, wl + 16384, bufA, n);
    k_agg128<<<ag, 256>>>(bufA, b2, bufB, n);
    // Layer 3 (FOUT=64) -> mu & logstd
    k_mma<64, true><<<gb, 256, SMEM64>>>(bufB, wh + 32768, wl + 32768, bufA, n);
    k_agg64<<<ag, 256>>>(bufA, b3, out, n);
}

// round 12
// speedup vs baseline: 1.4182x; 1.0200x over previous
#include <cuda_runtime.h>
#include <cuda_bf16.h>
#include <cstdint>

#define MAXN 100000
#define MAXE 1600000
#define DIN  128

// ---------------------------------------------------------------------------
// Scratch (allocation-free rule: __device__ globals)
// ---------------------------------------------------------------------------
__device__ float g_dinv[MAXN];
__device__ int   g_deg[MAXN];
__device__ int   g_rowptr[MAXN];
__device__ int   g_cursor[MAXN];
__device__ int   g_csrc[MAXE];
__device__ int   g_bsum[128];
__device__ int   g_is32 = 0;   // static init; only ever transitions 0->1 for
                               // the same input data => deterministic replays
__device__ float g_bufA[(size_t)MAXN * 128];
__device__ float g_bufB[(size_t)MAXN * 128];
// Pre-split weights: W1(128x128), W2(128x128), W3(64x128) -> 320*128 elems
__device__ __nv_bfloat16 g_wh[320 * 128];
__device__ __nv_bfloat16 g_wl[320 * 128];

// ---------------------------------------------------------------------------
// Zero degree histogram + dtype probe (first 512 int64-words; for int32 data
// they fuse (src[2i],src[2i+1]) pairs and fall out of [0,n) w.h.p.)
// ---------------------------------------------------------------------------
__global__ void k_zero_probe(const long long* __restrict__ raw, int pcnt, int n) {
    int i = blockIdx.x * blockDim.x + threadIdx.x;
    if (i < n) g_deg[i] = 0;
    if (i < pcnt) {
        long long v = raw[i];
        if (v < 0 || v >= (long long)n) g_is32 = 1;
    }
}

__global__ void k_hist(const void* __restrict__ raw, int e) {
    int i = blockIdx.x * blockDim.x + threadIdx.x;
    if (i >= e) return;
    int d = g_is32 ? ((const int*)raw)[e + i]
                   : (int)((const long long*)raw)[e + i];
    atomicAdd(&g_deg[d], 1);
}

// ---------------------------------------------------------------------------
// CSR build: exclusive scan (2 kernels) + fill
// ---------------------------------------------------------------------------
__global__ void k_scan1(int n) {
    __shared__ int sm[1024];
    int i = blockIdx.x * 1024 + threadIdx.x;
    int v = (i < n) ? g_deg[i] : 0;
    sm[threadIdx.x] = v;
    __syncthreads();
#pragma unroll
    for (int off = 1; off < 1024; off <<= 1) {
        int t = (threadIdx.x >= off) ? sm[threadIdx.x - off] : 0;
        __syncthreads();
        sm[threadIdx.x] += t;
        __syncthreads();
    }
    if (i < n) g_rowptr[i] = sm[threadIdx.x] - v;
    if (threadIdx.x == 1023) g_bsum[blockIdx.x] = sm[1023];
}

// Fused block-offset scan + apply + rsqrt norm. Every block redundantly scans
// the <=128 block sums (inclusive) in SMEM -- trivial cost, saves a launch.
__global__ void k_scan3(int n, int nb) {
    __shared__ int sb[128];
    int tid = threadIdx.x;
    if (tid < 128) sb[tid] = (tid < nb) ? g_bsum[tid] : 0;
    __syncthreads();
#pragma unroll
    for (int off = 1; off < 128; off <<= 1) {
        int v = 0;
        if (tid < 128 && tid >= off) v = sb[tid - off];
        __syncthreads();
        if (tid < 128) sb[tid] += v;
        __syncthreads();
    }
    int i = blockIdx.x * blockDim.x + tid;
    if (i < n) {
        int blk = i >> 10;
        int off = (blk == 0) ? 0 : sb[blk - 1];
        int r = g_rowptr[i] + off;
        g_rowptr[i] = r;
        g_cursor[i] = r;
        g_dinv[i] = rsqrtf((float)g_deg[i] + 1.0f);
    }
}

__global__ void k_fill(const void* __restrict__ raw, int e) {
    int i = blockIdx.x * blockDim.x + threadIdx.x;
    if (i >= e) return;
    int s, d;
    if (g_is32) {
        const int* p = (const int*)raw;
        s = p[i]; d = p[e + i];
    } else {
        const long long* p = (const long long*)raw;
        s = (int)p[i]; d = (int)p[e + i];
    }
    int pos = atomicAdd(&g_cursor[d], 1);
    g_csrc[pos] = s;
}

// ---------------------------------------------------------------------------
// Weight split: W (fp32) -> hi/lo bf16
// ---------------------------------------------------------------------------
__global__ void k_prep_w(const float* __restrict__ W1, const float* __restrict__ W2,
                         const float* __restrict__ W3) {
    int i = blockIdx.x * blockDim.x + threadIdx.x;
    if (i >= 320 * 128) return;
    float v;
    if (i < 16384)       v = W1[i];
    else if (i < 32768)  v = W2[i - 16384];
    else                 v = W3[i - 32768];
    __nv_bfloat16 h = __float2bfloat16_rn(v);
    g_wh[i] = h;
    g_wl[i] = __float2bfloat16_rn(v - __bfloat162float(h));
}

// ---------------------------------------------------------------------------
// mma.sync bf16 split GEMM: H[128 x FOUT tile] = act(X) @ W^T
// D = Ahi*Bhi + Alo*Bhi + Ahi*Blo  (fp32 accumulate, lo*lo dropped ~2^-16)
// ---------------------------------------------------------------------------
__device__ __forceinline__ void mma16816(float* c, const uint32_t* a,
                                         uint32_t b0, uint32_t b1) {
    asm volatile(
        "mma.sync.aligned.m16n8k16.row.col.f32.bf16.bf16.f32 "
        "{%0,%1,%2,%3}, {%4,%5,%6,%7}, {%8,%9}, {%0,%1,%2,%3};"
        : "+f"(c[0]), "+f"(c[1]), "+f"(c[2]), "+f"(c[3])
        : "r"(a[0]), "r"(a[1]), "r"(a[2]), "r"(a[3]), "r"(b0), "r"(b1));
}

template <int FOUT, bool RELU>
__global__ void __launch_bounds__(256, 1) k_mma(
    const float* __restrict__ X, const __nv_bfloat16* __restrict__ Wh,
    const __nv_bfloat16* __restrict__ Wl, float* __restrict__ H, int n)
{
    constexpr int RS = 136;     // smem row stride in bf16 (272B: conflict-free)
    constexpr int NT = FOUT / 8;
    extern __shared__ __nv_bfloat16 sm[];
    __nv_bfloat16* Ah = sm;                       // [8][16][RS]
    __nv_bfloat16* Al = Ah + 8 * 16 * RS;
    __nv_bfloat16* Bh = Al + 8 * 16 * RS;         // [FOUT][RS]
    __nv_bfloat16* Bl = Bh + FOUT * RS;

    const int tid = threadIdx.x, wid = tid >> 5, lane = tid & 31;
    const int row0 = blockIdx.x * 128;

    // ---- stage pre-split weights into SMEM ----
    for (int idx = tid; idx < FOUT * 32; idx += 256) {
        int r = idx >> 5, c4 = idx & 31;
        *(uint2*)&Bh[r * RS + c4 * 4] = *(const uint2*)&Wh[r * 128 + c4 * 4];
        *(uint2*)&Bl[r * RS + c4 * 4] = *(const uint2*)&Wl[r * 128 + c4 * 4];
    }

    // ---- each warp converts its 16 fp32 rows -> hi/lo bf16 (ReLU fused) ----
    __nv_bfloat16* Awh = Ah + wid * 16 * RS;
    __nv_bfloat16* Awl = Al + wid * 16 * RS;
    for (int idx = lane; idx < 16 * 32; idx += 32) {
        int r = idx >> 5, c4 = idx & 31;
        int grow = row0 + wid * 16 + r;
        float4 v = make_float4(0.f, 0.f, 0.f, 0.f);
        if (grow < n) {
            v = *(const float4*)&X[(size_t)grow * 128 + c4 * 4];
            if (RELU) {
                v.x = fmaxf(v.x, 0.f); v.y = fmaxf(v.y, 0.f);
                v.z = fmaxf(v.z, 0.f); v.w = fmaxf(v.w, 0.f);
            }
        }
        __nv_bfloat162 h01 = __floats2bfloat162_rn(v.x, v.y);
        __nv_bfloat162 h23 = __floats2bfloat162_rn(v.z, v.w);
        float2 f01 = __bfloat1622float2(h01);
        float2 f23 = __bfloat1622float2(h23);
        __nv_bfloat162 l01 = __floats2bfloat162_rn(v.x - f01.x, v.y - f01.y);
        __nv_bfloat162 l23 = __floats2bfloat162_rn(v.z - f23.x, v.w - f23.y);
        *(uint2*)&Awh[r * RS + c4 * 4] =
            make_uint2(*(uint32_t*)&h01, *(uint32_t*)&h23);
        *(uint2*)&Awl[r * RS + c4 * 4] =
            make_uint2(*(uint32_t*)&l01, *(uint32_t*)&l23);
    }
    __syncthreads();

    float acc[NT][4];
#pragma unroll
    for (int t = 0; t < NT; t++)
#pragma unroll
        for (int j = 0; j < 4; j++) acc[t][j] = 0.f;

    const int qr = lane >> 2;           // quad row
    const int qc = (lane & 3) * 2;      // quad col (k or n offset)

#pragma unroll
    for (int ks = 0; ks < 8; ks++) {
        const int kb = ks * 16;
        uint32_t ah[4], al[4];
        ah[0] = *(const uint32_t*)&Awh[(qr)     * RS + kb + qc];
        ah[1] = *(const uint32_t*)&Awh[(qr + 8) * RS + kb + qc];
        ah[2] = *(const uint32_t*)&Awh[(qr)     * RS + kb + 8 + qc];
        ah[3] = *(const uint32_t*)&Awh[(qr + 8) * RS + kb + 8 + qc];
        al[0] = *(const uint32_t*)&Awl[(qr)     * RS + kb + qc];
        al[1] = *(const uint32_t*)&Awl[(qr + 8) * RS + kb + qc];
        al[2] = *(const uint32_t*)&Awl[(qr)     * RS + kb + 8 + qc];
        al[3] = *(const uint32_t*)&Awl[(qr + 8) * RS + kb + 8 + qc];
#pragma unroll
        for (int nt = 0; nt < NT; nt++) {
            int nr = nt * 8 + qr;
            uint32_t bh0 = *(const uint32_t*)&Bh[nr * RS + kb + qc];
            uint32_t bh1 = *(const uint32_t*)&Bh[nr * RS + kb + 8 + qc];
            mma16816(acc[nt], ah, bh0, bh1);
            mma16816(acc[nt], al, bh0, bh1);
            uint32_t bl0 = *(const uint32_t*)&Bl[nr * RS + kb + qc];
            uint32_t bl1 = *(const uint32_t*)&Bl[nr * RS + kb + 8 + qc];
            mma16816(acc[nt], ah, bl0, bl1);
        }
    }

    // ---- epilogue ----
    const int r0 = row0 + wid * 16 + qr;
    const int r1 = r0 + 8;
#pragma unroll
    for (int nt = 0; nt < NT; nt++) {
        int col = nt * 8 + qc;
        if (r0 < n)
            *(float2*)&H[(size_t)r0 * FOUT + col] = make_float2(acc[nt][0], acc[nt][1]);
        if (r1 < n)
            *(float2*)&H[(size_t)r1 * FOUT + col] = make_float2(acc[nt][2], acc[nt][3]);
    }
}

// ---------------------------------------------------------------------------
// CSR aggregation: one warp per dst node, register accumulation, no atomics.
// OUT[d] = bias + dinv[d] * ( dinv[d]*H[d] + sum_{s in in(d)} dinv[s]*H[s] )
// High occupancy (no smem) is load-bearing: gather phase is L2-latency-bound.
// ---------------------------------------------------------------------------
__global__ void __launch_bounds__(256) k_agg128(
    const float* __restrict__ H, const float* __restrict__ bias,
    float* __restrict__ OUT, int n)
{
    int node = blockIdx.x * 8 + (threadIdx.x >> 5);
    if (node >= n) return;
    int lane = threadIdx.x & 31;

    int beg = g_rowptr[node];
    int end = beg + g_deg[node];

    float4 acc = make_float4(0.f, 0.f, 0.f, 0.f);
    int j = beg;
    for (; j + 4 <= end; j += 4) {
        int s0 = g_csrc[j], s1 = g_csrc[j + 1];
        int s2 = g_csrc[j + 2], s3 = g_csrc[j + 3];
        float w0 = g_dinv[s0], w1 = g_dinv[s1];
        float w2 = g_dinv[s2], w3 = g_dinv[s3];
        float4 v0 = *(const float4*)&H[(size_t)s0 * 128 + lane * 4];
        float4 v1 = *(const float4*)&H[(size_t)s1 * 128 + lane * 4];
        float4 v2 = *(const float4*)&H[(size_t)s2 * 128 + lane * 4];
        float4 v3 = *(const float4*)&H[(size_t)s3 * 128 + lane * 4];
        acc.x += w0 * v0.x + w1 * v1.x + w2 * v2.x + w3 * v3.x;
        acc.y += w0 * v0.y + w1 * v1.y + w2 * v2.y + w3 * v3.y;
        acc.z += w0 * v0.z + w1 * v1.z + w2 * v2.z + w3 * v3.z;
        acc.w += w0 * v0.w + w1 * v1.w + w2 * v2.w + w3 * v3.w;
    }
    for (; j < end; j++) {
        int s = g_csrc[j];
        float w = g_dinv[s];
        float4 v = *(const float4*)&H[(size_t)s * 128 + lane * 4];
        acc.x += w * v.x; acc.y += w * v.y;
        acc.z += w * v.z; acc.w += w * v.w;
    }

    float di = g_dinv[node];
    float4 hs = *(const float4*)&H[(size_t)node * 128 + lane * 4];
    float4 bb = *(const float4*)&bias[lane * 4];
    float4 o;
    o.x = bb.x + di * (acc.x + di * hs.x);
    o.y = bb.y + di * (acc.y + di * hs.y);
    o.z = bb.z + di * (acc.z + di * hs.z);
    o.w = bb.w + di * (acc.w + di * hs.w);
    *(float4*)&OUT[(size_t)node * 128 + lane * 4] = o;
}

__global__ void __launch_bounds__(256) k_agg64(
    const float* __restrict__ H, const float* __restrict__ bias,
    float* __restrict__ OUT, int n)
{
    int node = blockIdx.x * 8 + (threadIdx.x >> 5);
    if (node >= n) return;
    int lane = threadIdx.x & 31;

    int beg = g_rowptr[node];
    int end = beg + g_deg[node];

    float2 acc = make_float2(0.f, 0.f);
    int j = beg;
    for (; j + 4 <= end; j += 4) {
        int s0 = g_csrc[j], s1 = g_csrc[j + 1];
        int s2 = g_csrc[j + 2], s3 = g_csrc[j + 3];
        float w0 = g_dinv[s0], w1 = g_dinv[s1];
        float w2 = g_dinv[s2], w3 = g_dinv[s3];
        float2 v0 = *(const float2*)&H[(size_t)s0 * 64 + lane * 2];
        float2 v1 = *(const float2*)&H[(size_t)s1 * 64 + lane * 2];
        float2 v2 = *(const float2*)&H[(size_t)s2 * 64 + lane * 2];
        float2 v3 = *(const float2*)&H[(size_t)s3 * 64 + lane * 2];
        acc.x += w0 * v0.x + w1 * v1.x + w2 * v2.x + w3 * v3.x;
        acc.y += w0 * v0.y + w1 * v1.y + w2 * v2.y + w3 * v3.y;
    }
    for (; j < end; j++) {
        int s = g_csrc[j];
        float w = g_dinv[s];
        float2 v = *(const float2*)&H[(size_t)s * 64 + lane * 2];
        acc.x += w * v.x; acc.y += w * v.y;
    }

    float di = g_dinv[node];
    float2 hs = *(const float2*)&H[(size_t)node * 64 + lane * 2];
    float2 bb = *(const float2*)&bias[lane * 2];
    float2 o;
    o.x = bb.x + di * (acc.x + di * hs.x);
    o.y = bb.y + di * (acc.y + di * hs.y);
    *(float2*)&OUT[(size_t)node * 64 + lane * 2] = o;         // mu
    *(float2*)&OUT[(size_t)(n + node) * 64 + lane * 2] = o;   // logstd
}

// ---------------------------------------------------------------------------
extern "C" void kernel_launch(void* const* d_in, const int* in_sizes, int n_in,
                              void* d_out, int out_size)
{
    const float* x  = (const float*)d_in[0];
    const float* W1 = (const float*)d_in[1];
    const float* b1 = (const float*)d_in[2];
    const float* W2 = (const float*)d_in[3];
    const float* b2 = (const float*)d_in[4];
    const float* W3 = (const float*)d_in[5];
    const float* b3 = (const float*)d_in[6];
    const void*  ei = d_in[7];

    int n = in_sizes[0] / DIN;
    int e = in_sizes[7] / 2;
    float* out = (float*)d_out;

    // Lazy one-time stream/event creation (host-side resources only; first
    // call happens after the harness has initialized the CUDA context, well
    // before graph capture; per-call GPU work is identical on every call).
    static cudaStream_t s_aux = nullptr;
    static cudaEvent_t  s_fork = nullptr, s_join = nullptr;
    if (!s_aux) {
        cudaStreamCreateWithFlags(&s_aux, cudaStreamNonBlocking);
        cudaEventCreateWithFlags(&s_fork, cudaEventDisableTiming);
        cudaEventCreateWithFlags(&s_join, cudaEventDisableTiming);
    }

    float *bufA, *bufB;
    cudaGetSymbolAddress((void**)&bufA, g_bufA);
    cudaGetSymbolAddress((void**)&bufB, g_bufB);
    __nv_bfloat16 *wh, *wl;
    cudaGetSymbolAddress((void**)&wh, g_wh);
    cudaGetSymbolAddress((void**)&wl, g_wl);

    constexpr int RS = 136;
    const int SMEM128 = (8 * 16 * RS * 2 + 128 * RS * 2) * 2;  // ~136 KB
    const int SMEM64  = (8 * 16 * RS * 2 + 64 * RS * 2) * 2;   // ~102 KB
    cudaFuncSetAttribute(k_mma<128, false>,
                         cudaFuncAttributeMaxDynamicSharedMemorySize, SMEM128);
    cudaFuncSetAttribute(k_mma<128, true>,
                         cudaFuncAttributeMaxDynamicSharedMemorySize, SMEM128);
    cudaFuncSetAttribute(k_mma<64, true>,
                         cudaFuncAttributeMaxDynamicSharedMemorySize, SMEM64);

    int nb  = (n + 255) / 256;
    int ebk = (e + 255) / 256;
    int nsb = (n + 1023) / 1024;

    int gb = (n + 127) / 128;   // GEMM tiles
    int ag = (n + 7) / 8;       // agg blocks

    // --- fork: CSR build on aux stream, weight-split + GEMM1 on main ---
    cudaEventRecord(s_fork, 0);
    cudaStreamWaitEvent(s_aux, s_fork, 0);

    k_zero_probe<<<nb, 256, 0, s_aux>>>((const long long*)ei,
                                        512 < e ? 512 : e, n);
    k_hist<<<ebk, 256, 0, s_aux>>>(ei, e);
    k_scan1<<<nsb, 1024, 0, s_aux>>>(n);
    k_scan3<<<nb, 256, 0, s_aux>>>(n, nsb);
    k_fill<<<ebk, 256, 0, s_aux>>>(ei, e);
    cudaEventRecord(s_join, s_aux);

    k_prep_w<<<160, 256>>>(W1, W2, W3);
    // Layer 1 GEMM (independent of CSR)
    k_mma<128, false><<<gb, 256, SMEM128>>>(x, wh, wl, bufA, n);

    // --- join: aggregations need the CSR ---
    cudaStreamWaitEvent(0, s_join, 0);

    k_agg128<<<ag, 256>>>(bufA, b1, bufB, n);
    // Layer 2
    k_mma<128, true><<<gb, 256, SMEM128>>>(bufB, wh + 16384, wl + 16384, bufA, n);
    k_agg128<<<ag, 256>>>(bufA, b2, bufB, n);
    // Layer 3 (FOUT=64) -> mu & logstd
    k_mma<64, true><<<gb, 256, SMEM64>>>(bufB, wh + 32768, wl + 32768, bufA, n);
    k_agg64<<<ag, 256>>>(bufA, b3, out, n);
}

// round 14
// speedup vs baseline: 1.4476x; 1.0207x over previous
#include <cuda_runtime.h>
#include <cuda_bf16.h>
#include <cstdint>

#define MAXN 100000
#define MAXE 1600000
#define DIN  128

// ---------------------------------------------------------------------------
// Scratch (allocation-free rule: __device__ globals)
// ---------------------------------------------------------------------------
__device__ float g_dinv[MAXN];
__device__ int   g_deg[MAXN];
__device__ int   g_rowptr[MAXN];
__device__ int   g_cursor[MAXN];
__device__ int   g_csrc[MAXE];
__device__ int   g_bsum[128];
__device__ int   g_is32 = 0;   // static init; only ever transitions 0->1 for
                               // the same input data => deterministic replays
__device__ float g_bufA[(size_t)MAXN * 128];
__device__ float g_bufB[(size_t)MAXN * 128];
// Pre-split weights: W1(128x128), W2(128x128), W3(64x128) -> 320*128 elems
__device__ __nv_bfloat16 g_wh[320 * 128];
__device__ __nv_bfloat16 g_wl[320 * 128];

// ---------------------------------------------------------------------------
// Zero degree histogram + dtype probe (first 512 int64-words; for int32 data
// they fuse (src[2i],src[2i+1]) pairs and fall out of [0,n) w.h.p.)
// ---------------------------------------------------------------------------
__global__ void k_zero_probe(const long long* __restrict__ raw, int pcnt, int n) {
    int i = blockIdx.x * blockDim.x + threadIdx.x;
    if (i < n) g_deg[i] = 0;
    if (i < pcnt) {
        long long v = raw[i];
        if (v < 0 || v >= (long long)n) g_is32 = 1;
    }
}

__global__ void k_hist(const void* __restrict__ raw, int e) {
    int i = blockIdx.x * blockDim.x + threadIdx.x;
    if (i >= e) return;
    int d = g_is32 ? ((const int*)raw)[e + i]
                   : (int)((const long long*)raw)[e + i];
    atomicAdd(&g_deg[d], 1);
}

// ---------------------------------------------------------------------------
// CSR build: exclusive scan + fill
// ---------------------------------------------------------------------------
__global__ void k_scan1(int n) {
    __shared__ int sm[1024];
    int i = blockIdx.x * 1024 + threadIdx.x;
    int v = (i < n) ? g_deg[i] : 0;
    sm[threadIdx.x] = v;
    __syncthreads();
#pragma unroll
    for (int off = 1; off < 1024; off <<= 1) {
        int t = (threadIdx.x >= off) ? sm[threadIdx.x - off] : 0;
        __syncthreads();
        sm[threadIdx.x] += t;
        __syncthreads();
    }
    if (i < n) g_rowptr[i] = sm[threadIdx.x] - v;
    if (threadIdx.x == 1023) g_bsum[blockIdx.x] = sm[1023];
}

// Fused block-offset scan + apply + rsqrt norm.
__global__ void k_scan3(int n, int nb) {
    __shared__ int sb[128];
    int tid = threadIdx.x;
    if (tid < 128) sb[tid] = (tid < nb) ? g_bsum[tid] : 0;
    __syncthreads();
#pragma unroll
    for (int off = 1; off < 128; off <<= 1) {
        int v = 0;
        if (tid < 128 && tid >= off) v = sb[tid - off];
        __syncthreads();
        if (tid < 128) sb[tid] += v;
        __syncthreads();
    }
    int i = blockIdx.x * blockDim.x + tid;
    if (i < n) {
        int blk = i >> 10;
        int off = (blk == 0) ? 0 : sb[blk - 1];
        int r = g_rowptr[i] + off;
        g_rowptr[i] = r;
        g_cursor[i] = r;
        g_dinv[i] = rsqrtf((float)g_deg[i] + 1.0f);
    }
}

__global__ void k_fill(const void* __restrict__ raw, int e) {
    int i = blockIdx.x * blockDim.x + threadIdx.x;
    if (i >= e) return;
    int s, d;
    if (g_is32) {
        const int* p = (const int*)raw;
        s = p[i]; d = p[e + i];
    } else {
        const long long* p = (const long long*)raw;
        s = (int)p[i]; d = (int)p[e + i];
    }
    int pos = atomicAdd(&g_cursor[d], 1);
    g_csrc[pos] = s;
}

// ---------------------------------------------------------------------------
// Weight split: W (fp32) -> hi/lo bf16
// ---------------------------------------------------------------------------
__global__ void k_prep_w(const float* __restrict__ W1, const float* __restrict__ W2,
                         const float* __restrict__ W3) {
    int i = blockIdx.x * blockDim.x + threadIdx.x;
    if (i >= 320 * 128) return;
    float v;
    if (i < 16384)       v = W1[i];
    else if (i < 32768)  v = W2[i - 16384];
    else                 v = W3[i - 32768];
    __nv_bfloat16 h = __float2bfloat16_rn(v);
    g_wh[i] = h;
    g_wl[i] = __float2bfloat16_rn(v - __bfloat162float(h));
}

// ---------------------------------------------------------------------------
// mma.sync bf16 split GEMM: H[128 x FOUT tile] = act(X) @ W^T
// D = Ahi*Bhi + Alo*Bhi + Ahi*Blo  (fp32 accumulate, lo*lo dropped ~2^-16)
// Fragment loads via ldmatrix.x4 (1 instr per four 8x8 fragments).
// ---------------------------------------------------------------------------
__device__ __forceinline__ void mma16816(float* c, const uint32_t* a,
                                         uint32_t b0, uint32_t b1) {
    asm volatile(
        "mma.sync.aligned.m16n8k16.row.col.f32.bf16.bf16.f32 "
        "{%0,%1,%2,%3}, {%4,%5,%6,%7}, {%8,%9}, {%0,%1,%2,%3};"
        : "+f"(c[0]), "+f"(c[1]), "+f"(c[2]), "+f"(c[3])
        : "r"(a[0]), "r"(a[1]), "r"(a[2]), "r"(a[3]), "r"(b0), "r"(b1));
}

__device__ __forceinline__ void ldsm_x4(uint32_t* r, uint32_t saddr) {
    asm volatile("ldmatrix.sync.aligned.m8n8.x4.shared.b16 {%0,%1,%2,%3}, [%4];"
                 : "=r"(r[0]), "=r"(r[1]), "=r"(r[2]), "=r"(r[3]) : "r"(saddr));
}

template <int FOUT, bool RELU>
__global__ void __launch_bounds__(256, 1) k_mma(
    const float* __restrict__ X, const __nv_bfloat16* __restrict__ Wh,
    const __nv_bfloat16* __restrict__ Wl, float* __restrict__ H, int n)
{
    constexpr int RS = 136;     // smem row stride in bf16 (272B; 16B-aligned,
                                // rows cycle 8 distinct 16B offsets mod 128B
                                // => conflict-free ldmatrix)
    constexpr int NT = FOUT / 8;
    extern __shared__ __nv_bfloat16 sm[];
    __nv_bfloat16* Ah = sm;                       // [8][16][RS]
    __nv_bfloat16* Al = Ah + 8 * 16 * RS;
    __nv_bfloat16* Bh = Al + 8 * 16 * RS;         // [FOUT][RS]
    __nv_bfloat16* Bl = Bh + FOUT * RS;

    const int tid = threadIdx.x, wid = tid >> 5, lane = tid & 31;
    const int row0 = blockIdx.x * 128;

    // ---- stage pre-split weights into SMEM ----
    for (int idx = tid; idx < FOUT * 32; idx += 256) {
        int r = idx >> 5, c4 = idx & 31;
        *(uint2*)&Bh[r * RS + c4 * 4] = *(const uint2*)&Wh[r * 128 + c4 * 4];
        *(uint2*)&Bl[r * RS + c4 * 4] = *(const uint2*)&Wl[r * 128 + c4 * 4];
    }

    // ---- each warp converts its 16 fp32 rows -> hi/lo bf16 (ReLU fused) ----
    __nv_bfloat16* Awh = Ah + wid * 16 * RS;
    __nv_bfloat16* Awl = Al + wid * 16 * RS;
    for (int idx = lane; idx < 16 * 32; idx += 32) {
        int r = idx >> 5, c4 = idx & 31;
        int grow = row0 + wid * 16 + r;
        float4 v = make_float4(0.f, 0.f, 0.f, 0.f);
        if (grow < n) {
            v = *(const float4*)&X[(size_t)grow * 128 + c4 * 4];
            if (RELU) {
                v.x = fmaxf(v.x, 0.f); v.y = fmaxf(v.y, 0.f);
                v.z = fmaxf(v.z, 0.f); v.w = fmaxf(v.w, 0.f);
            }
        }
        __nv_bfloat162 h01 = __floats2bfloat162_rn(v.x, v.y);
        __nv_bfloat162 h23 = __floats2bfloat162_rn(v.z, v.w);
        float2 f01 = __bfloat1622float2(h01);
        float2 f23 = __bfloat1622float2(h23);
        __nv_bfloat162 l01 = __floats2bfloat162_rn(v.x - f01.x, v.y - f01.y);
        __nv_bfloat162 l23 = __floats2bfloat162_rn(v.z - f23.x, v.w - f23.y);
        *(uint2*)&Awh[r * RS + c4 * 4] =
            make_uint2(*(uint32_t*)&h01, *(uint32_t*)&h23);
        *(uint2*)&Awl[r * RS + c4 * 4] =
            make_uint2(*(uint32_t*)&l01, *(uint32_t*)&l23);
    }
    __syncthreads();

    float acc[NT][4];
#pragma unroll
    for (int t = 0; t < NT; t++)
#pragma unroll
        for (int j = 0; j < 4; j++) acc[t][j] = 0.f;

    const int qr = lane >> 2;           // quad row
    const int qc = (lane & 3) * 2;      // quad col

    // ldmatrix per-lane addressing (in bf16 elements, relative to tile base):
    // A x4: matrices (m0-7,k0-7)(m8-15,k0-7)(m0-7,k8-15)(m8-15,k8-15)
    //   lane -> row (lane&15), col 8*(lane>>4)            => regs = a0..a3
    // B x4 covers TWO n-tiles: (n0-7,k0-7)(n0-7,k8-15)(n8-15,k0-7)(n8-15,k8-15)
    //   lane -> row ((lane>>4)<<3)+(lane&7), col 8*((lane>>3)&1)
    //   => regs = b0,b1 (tile nt), b0,b1 (tile nt+1)
    const uint32_t a_off = (uint32_t)(((lane & 15) * RS + ((lane >> 4) << 3)) * 2);
    const uint32_t b_off = (uint32_t)(((((lane >> 4) << 3) + (lane & 7)) * RS
                                      + (((lane >> 3) & 1) << 3)) * 2);
    const uint32_t sAh = (uint32_t)__cvta_generic_to_shared(Awh) + a_off;
    const uint32_t sAl = (uint32_t)__cvta_generic_to_shared(Awl) + a_off;
    const uint32_t sBh = (uint32_t)__cvta_generic_to_shared(Bh) + b_off;
    const uint32_t sBl = (uint32_t)__cvta_generic_to_shared(Bl) + b_off;

#pragma unroll
    for (int ks = 0; ks < 8; ks++) {
        const uint32_t kadd = (uint32_t)(ks * 16 * 2);  // kb in bytes
        uint32_t ah[4], al[4];
        ldsm_x4(ah, sAh + kadd);
        ldsm_x4(al, sAl + kadd);
#pragma unroll
        for (int ntp = 0; ntp < NT / 2; ntp++) {
            const uint32_t badd = kadd + (uint32_t)(ntp * 16 * RS * 2);
            uint32_t bh[4], bl[4];
            ldsm_x4(bh, sBh + badd);
            ldsm_x4(bl, sBl + badd);
            mma16816(acc[ntp * 2],     ah, bh[0], bh[1]);
            mma16816(acc[ntp * 2],     al, bh[0], bh[1]);
            mma16816(acc[ntp * 2],     ah, bl[0], bl[1]);
            mma16816(acc[ntp * 2 + 1], ah, bh[2], bh[3]);
            mma16816(acc[ntp * 2 + 1], al, bh[2], bh[3]);
            mma16816(acc[ntp * 2 + 1], ah, bl[2], bl[3]);
        }
    }

    // ---- epilogue ----
    const int r0 = row0 + wid * 16 + qr;
    const int r1 = r0 + 8;
#pragma unroll
    for (int nt = 0; nt < NT; nt++) {
        int col = nt * 8 + qc;
        if (r0 < n)
            *(float2*)&H[(size_t)r0 * FOUT + col] = make_float2(acc[nt][0], acc[nt][1]);
        if (r1 < n)
            *(float2*)&H[(size_t)r1 * FOUT + col] = make_float2(acc[nt][2], acc[nt][3]);
    }
}

// ---------------------------------------------------------------------------
// CSR aggregation: one warp per dst node, register accumulation, no atomics.
// OUT[d] = bias + dinv[d] * ( dinv[d]*H[d] + sum_{s in in(d)} dinv[s]*H[s] )
// High occupancy (no smem) is load-bearing: gather phase is L2-latency-bound.
// ---------------------------------------------------------------------------
__global__ void __launch_bounds__(256) k_agg128(
    const float* __restrict__ H, const float* __restrict__ bias,
    float* __restrict__ OUT, int n)
{
    int node = blockIdx.x * 8 + (threadIdx.x >> 5);
    if (node >= n) return;
    int lane = threadIdx.x & 31;

    int beg = g_rowptr[node];
    int end = beg + g_deg[node];

    float4 acc = make_float4(0.f, 0.f, 0.f, 0.f);
    int j = beg;
    for (; j + 4 <= end; j += 4) {
        int s0 = g_csrc[j], s1 = g_csrc[j + 1];
        int s2 = g_csrc[j + 2], s3 = g_csrc[j + 3];
        float w0 = g_dinv[s0], w1 = g_dinv[s1];
        float w2 = g_dinv[s2], w3 = g_dinv[s3];
        float4 v0 = *(const float4*)&H[(size_t)s0 * 128 + lane * 4];
        float4 v1 = *(const float4*)&H[(size_t)s1 * 128 + lane * 4];
        float4 v2 = *(const float4*)&H[(size_t)s2 * 128 + lane * 4];
        float4 v3 = *(const float4*)&H[(size_t)s3 * 128 + lane * 4];
        acc.x += w0 * v0.x + w1 * v1.x + w2 * v2.x + w3 * v3.x;
        acc.y += w0 * v0.y + w1 * v1.y + w2 * v2.y + w3 * v3.y;
        acc.z += w0 * v0.z + w1 * v1.z + w2 * v2.z + w3 * v3.z;
        acc.w += w0 * v0.w + w1 * v1.w + w2 * v2.w + w3 * v3.w;
    }
    for (; j < end; j++) {
        int s = g_csrc[j];
        float w = g_dinv[s];
        float4 v = *(const float4*)&H[(size_t)s * 128 + lane * 4];
        acc.x += w * v.x; acc.y += w * v.y;
        acc.z += w * v.z; acc.w += w * v.w;
    }

    float di = g_dinv[node];
    float4 hs = *(const float4*)&H[(size_t)node * 128 + lane * 4];
    float4 bb = *(const float4*)&bias[lane * 4];
    float4 o;
    o.x = bb.x + di * (acc.x + di * hs.x);
    o.y = bb.y + di * (acc.y + di * hs.y);
    o.z = bb.z + di * (acc.z + di * hs.z);
    o.w = bb.w + di * (acc.w + di * hs.w);
    *(float4*)&OUT[(size_t)node * 128 + lane * 4] = o;
}

__global__ void __launch_bounds__(256) k_agg64(
    const float* __restrict__ H, const float* __restrict__ bias,
    float* __restrict__ OUT, int n)
{
    int node = blockIdx.x * 8 + (threadIdx.x >> 5);
    if (node >= n) return;
    int lane = threadIdx.x & 31;

    int beg = g_rowptr[node];
    int end = beg + g_deg[node];

    float2 acc = make_float2(0.f, 0.f);
    int j = beg;
    for (; j + 4 <= end; j += 4) {
        int s0 = g_csrc[j], s1 = g_csrc[j + 1];
        int s2 = g_csrc[j + 2], s3 = g_csrc[j + 3];
        float w0 = g_dinv[s0], w1 = g_dinv[s1];
        float w2 = g_dinv[s2], w3 = g_dinv[s3];
        float2 v0 = *(const float2*)&H[(size_t)s0 * 64 + lane * 2];
        float2 v1 = *(const float2*)&H[(size_t)s1 * 64 + lane * 2];
        float2 v2 = *(const float2*)&H[(size_t)s2 * 64 + lane * 2];
        float2 v3 = *(const float2*)&H[(size_t)s3 * 64 + lane * 2];
        acc.x += w0 * v0.x + w1 * v1.x + w2 * v2.x + w3 * v3.x;
        acc.y += w0 * v0.y + w1 * v1.y + w2 * v2.y + w3 * v3.y;
    }
    for (; j < end; j++) {
        int s = g_csrc[j];
        float w = g_dinv[s];
        float2 v = *(const float2*)&H[(size_t)s * 64 + lane * 2];
        acc.x += w * v.x; acc.y += w * v.y;
    }

    float di = g_dinv[node];
    float2 hs = *(const float2*)&H[(size_t)node * 64 + lane * 2];
    float2 bb = *(const float2*)&bias[lane * 2];
    float2 o;
    o.x = bb.x + di * (acc.x + di * hs.x);
    o.y = bb.y + di * (acc.y + di * hs.y);
    *(float2*)&OUT[(size_t)node * 64 + lane * 2] = o;         // mu
    *(float2*)&OUT[(size_t)(n + node) * 64 + lane * 2] = o;   // logstd
}

// ---------------------------------------------------------------------------
extern "C" void kernel_launch(void* const* d_in, const int* in_sizes, int n_in,
                              void* d_out, int out_size)
{
    const float* x  = (const float*)d_in[0];
    const float* W1 = (const float*)d_in[1];
    const float* b1 = (const float*)d_in[2];
    const float* W2 = (const float*)d_in[3];
    const float* b2 = (const float*)d_in[4];
    const float* W3 = (const float*)d_in[5];
    const float* b3 = (const float*)d_in[6];
    const void*  ei = d_in[7];

    int n = in_sizes[0] / DIN;
    int e = in_sizes[7] / 2;
    float* out = (float*)d_out;

    // Lazy one-time stream/event creation (host-side resources only).
    static cudaStream_t s_aux = nullptr;
    static cudaEvent_t  s_fork = nullptr, s_join = nullptr;
    if (!s_aux) {
        cudaStreamCreateWithFlags(&s_aux, cudaStreamNonBlocking);
        cudaEventCreateWithFlags(&s_fork, cudaEventDisableTiming);
        cudaEventCreateWithFlags(&s_join, cudaEventDisableTiming);
    }

    float *bufA, *bufB;
    cudaGetSymbolAddress((void**)&bufA, g_bufA);
    cudaGetSymbolAddress((void**)&bufB, g_bufB);
    __nv_bfloat16 *wh, *wl;
    cudaGetSymbolAddress((void**)&wh, g_wh);
    cudaGetSymbolAddress((void**)&wl, g_wl);

    constexpr int RS = 136;
    const int SMEM128 = (8 * 16 * RS * 2 + 128 * RS * 2) * 2;  // ~136 KB
    const int SMEM64  = (8 * 16 * RS * 2 + 64 * RS * 2) * 2;   // ~102 KB
    cudaFuncSetAttribute(k_mma<128, false>,
                         cudaFuncAttributeMaxDynamicSharedMemorySize, SMEM128);
    cudaFuncSetAttribute(k_mma<128, true>,
                         cudaFuncAttributeMaxDynamicSharedMemorySize, SMEM128);
    cudaFuncSetAttribute(k_mma<64, true>,
                         cudaFuncAttributeMaxDynamicSharedMemorySize, SMEM64);

    int nb  = (n + 255) / 256;
    int ebk = (e + 255) / 256;
    int nsb = (n + 1023) / 1024;

    int gb = (n + 127) / 128;   // GEMM tiles
    int ag = (n + 7) / 8;       // agg blocks

    // --- fork: CSR build on aux stream, weight-split + GEMM1 on main ---
    cudaEventRecord(s_fork, 0);
    cudaStreamWaitEvent(s_aux, s_fork, 0);

    k_zero_probe<<<nb, 256, 0, s_aux>>>((const long long*)ei,
                                        512 < e ? 512 : e, n);
    k_hist<<<ebk, 256, 0, s_aux>>>(ei, e);
    k_scan1<<<nsb, 1024, 0, s_aux>>>(n);
    k_scan3<<<nb, 256, 0, s_aux>>>(n, nsb);
    k_fill<<<ebk, 256, 0, s_aux>>>(ei, e);
    cudaEventRecord(s_join, s_aux);

    k_prep_w<<<160, 256>>>(W1, W2, W3);
    // Layer 1 GEMM (independent of CSR)
    k_mma<128, false><<<gb, 256, SMEM128>>>(x, wh, wl, bufA, n);

    // --- join: aggregations need the CSR ---
    cudaStreamWaitEvent(0, s_join, 0);

    k_agg128<<<ag, 256>>>(bufA, b1, bufB, n);
    // Layer 2
    k_mma<128, true><<<gb, 256, SMEM128>>>(bufB, wh + 16384, wl + 16384, bufA, n);
    k_agg128<<<ag, 256>>>(bufA, b2, bufB, n);
    // Layer 3 (FOUT=64) -> mu & logstd
    k_mma<64, true><<<gb, 256, SMEM64>>>(bufB, wh + 32768, wl + 32768, bufA, n);
    k_agg64<<<ag, 256>>>(bufA, b3, out, n);
}